// round 2
// baseline (speedup 1.0000x reference)
#include <cuda_runtime.h>

// Problem dims
#define B_  128
#define T_  512
#define D_  512
#define H_  512
#define L_  256

// ---------------------------------------------------------------------------
// Device scratch (allocation-free rule: __device__ globals)
// ---------------------------------------------------------------------------
__device__ float g_ig[(size_t)T_ * B_ * 3 * H_];   // (T, B, 3H) input gates
__device__ float g_h[B_ * H_];                      // recurrent state
__device__ unsigned long long g_bar = 0;            // monotonic grid barrier

// ---------------------------------------------------------------------------
// Helpers
// ---------------------------------------------------------------------------
__device__ __forceinline__ unsigned f2tf(float f) {
    unsigned u;
    asm("cvt.rna.tf32.f32 %0, %1;" : "=r"(u) : "f"(f));
    return u;
}

__device__ __forceinline__ void mma8(float c[4],
                                     unsigned a0, unsigned a1, unsigned a2, unsigned a3,
                                     unsigned b0, unsigned b1) {
    asm volatile(
        "mma.sync.aligned.m16n8k8.row.col.f32.tf32.tf32.f32 "
        "{%0,%1,%2,%3}, {%4,%5,%6,%7}, {%8,%9}, {%0,%1,%2,%3};"
        : "+f"(c[0]), "+f"(c[1]), "+f"(c[2]), "+f"(c[3])
        : "r"(a0), "r"(a1), "r"(a2), "r"(a3), "r"(b0), "r"(b1));
}

__device__ __forceinline__ float sigf(float x) {
    return 1.0f / (1.0f + __expf(-x));
}

// ===========================================================================
// Kernel 1: IG[t,b,:] = x[b,t,:] @ Wih^T + b
//   grid (12, 512)  [x = N-block so A-tile sharing CTAs are adjacent -> L2]
//   block 256 (8 warps), CTA tile 128(M=batch for one t) x 128(N), k-chunk 16
//   warp grid 2(M) x 4(N), warp tile 64x32
// ===========================================================================
__global__ void __launch_bounds__(256) k_igemm(const float* __restrict__ x,
                                               const float* __restrict__ Wih,
                                               const float* __restrict__ bias) {
    __shared__ unsigned As[128][20];  // pitch 20: conflict-free frag reads
    __shared__ unsigned Bs[128][20];

    const int t   = blockIdx.y;
    const int n0  = blockIdx.x * 128;
    const int tid = threadIdx.x;
    const int w    = tid >> 5;
    const int lane = tid & 31;
    const int gid  = lane >> 2;
    const int tig  = lane & 3;
    const int mrow = (w >> 2) * 64;   // 0 or 64
    const int ncol = (w & 3) * 32;    // 0,32,64,96

    float acc[4][4][4];
    #pragma unroll
    for (int i = 0; i < 4; i++)
        #pragma unroll
        for (int j = 0; j < 4; j++)
            #pragma unroll
            for (int q = 0; q < 4; q++) acc[i][j][q] = 0.0f;

    for (int k0 = 0; k0 < 512; k0 += 16) {
        // Load A tile: rows = batch b (0..127), cols = k0..k0+16
        #pragma unroll
        for (int it = 0; it < 2; it++) {
            int i  = tid + it * 256;        // float4 index 0..511
            int r  = i >> 2;
            int c4 = (i & 3) * 4;
            float4 v = *(const float4*)(x + ((size_t)r * 512 + t) * 512 + k0 + c4);
            As[r][c4 + 0] = f2tf(v.x);
            As[r][c4 + 1] = f2tf(v.y);
            As[r][c4 + 2] = f2tf(v.z);
            As[r][c4 + 3] = f2tf(v.w);
        }
        // Load B tile: rows = Wih rows n0..n0+128, cols = k0..k0+16
        #pragma unroll
        for (int it = 0; it < 2; it++) {
            int i  = tid + it * 256;
            int r  = i >> 2;
            int c4 = (i & 3) * 4;
            float4 v = *(const float4*)(Wih + (size_t)(n0 + r) * 512 + k0 + c4);
            Bs[r][c4 + 0] = f2tf(v.x);
            Bs[r][c4 + 1] = f2tf(v.y);
            Bs[r][c4 + 2] = f2tf(v.z);
            Bs[r][c4 + 3] = f2tf(v.w);
        }
        __syncthreads();

        #pragma unroll
        for (int ks = 0; ks < 2; ks++) {
            const int kb = ks * 8;
            unsigned a[4][4];
            #pragma unroll
            for (int mt = 0; mt < 4; mt++) {
                int r = mrow + mt * 16 + gid;
                a[mt][0] = As[r][kb + tig];
                a[mt][1] = As[r + 8][kb + tig];
                a[mt][2] = As[r][kb + tig + 4];
                a[mt][3] = As[r + 8][kb + tig + 4];
            }
            #pragma unroll
            for (int nt = 0; nt < 4; nt++) {
                int n = ncol + nt * 8 + gid;
                unsigned b0 = Bs[n][kb + tig];
                unsigned b1 = Bs[n][kb + tig + 4];
                #pragma unroll
                for (int mt = 0; mt < 4; mt++)
                    mma8(acc[mt][nt], a[mt][0], a[mt][1], a[mt][2], a[mt][3], b0, b1);
            }
        }
        __syncthreads();
    }

    // Epilogue: IG[(t*128 + b)*1536 + n] = acc + bias[n]
    #pragma unroll
    for (int mt = 0; mt < 4; mt++) {
        #pragma unroll
        for (int nt = 0; nt < 4; nt++) {
            int r0 = mrow + mt * 16 + gid;
            int c0 = n0 + ncol + nt * 8 + 2 * tig;
            float bv0 = __ldg(bias + c0);
            float bv1 = __ldg(bias + c0 + 1);
            size_t base0 = ((size_t)t * 128 + r0) * 1536 + c0;
            size_t base1 = ((size_t)t * 128 + r0 + 8) * 1536 + c0;
            *(float2*)&g_ig[base0] = make_float2(acc[mt][nt][0] + bv0, acc[mt][nt][1] + bv1);
            *(float2*)&g_ig[base1] = make_float2(acc[mt][nt][2] + bv0, acc[mt][nt][3] + bv1);
        }
    }
}

// ===========================================================================
// Kernel 2: persistent GRU recurrence. grid=128 (4 row-groups x 32 col-groups),
// block=128. Each CTA: h rows [mg*32, mg*32+32), h cols [cg*16, cg*16+16).
// Whh slice (48x512) cached in SMEM as TF32, pitch 516 (conflict-free).
// h re-staged from gmem (__ldcg) each step after the grid barrier.
// ===========================================================================
#define WS_PITCH 516
#define SG_PITCH 52
#define SMEM_K2_WORDS (48 * WS_PITCH + 32 * WS_PITCH + 32 * SG_PITCH)
#define SMEM_K2_BYTES (SMEM_K2_WORDS * 4)

__global__ void __launch_bounds__(128) k_rec(const float* __restrict__ Whh,
                                             const float* __restrict__ bn) {
    extern __shared__ unsigned smem[];
    unsigned* Ws = smem;                          // [48][516] tf32 Whh slice
    unsigned* Hs = smem + 48 * WS_PITCH;          // [32][516] tf32 h tile
    float*    Sg = (float*)(smem + 48 * WS_PITCH + 32 * WS_PITCH);  // [32][52] hg

    const int tid  = threadIdx.x;
    const int lane = tid & 31;
    const int w    = tid >> 5;
    const int gid  = lane >> 2;
    const int tig  = lane & 3;
    const int mg   = blockIdx.x >> 5;     // 0..3
    const int cg   = blockIdx.x & 31;     // 0..31
    const int rowbase = mg * 32;
    const int colbase = cg * 16;
    const int G = gridDim.x;              // 128

    // Load Whh slice: local row lr = gate*16 + jj  <->  Whh row gate*512 + colbase + jj
    for (int i = tid; i < 48 * 128; i += 128) {
        int lr   = i >> 7;
        int c4   = (i & 127) * 4;
        int grow = (lr >> 4) * 512 + colbase + (lr & 15);
        float4 v = *(const float4*)(Whh + (size_t)grow * 512 + c4);
        uint4 u = make_uint4(f2tf(v.x), f2tf(v.y), f2tf(v.z), f2tf(v.w));
        *(uint4*)&Ws[lr * WS_PITCH + c4] = u;
    }
    // Zero Hs (h0 = 0)
    for (int i = tid; i < 32 * WS_PITCH; i += 128) Hs[i] = 0u;
    __syncthreads();

    // MMA partition: warp grid 2(M) x 2(N); warp tile 16(M) x 24(N)
    const int mrow = (w >> 1) * 16;   // 0 or 16
    const int ncol = (w & 1) * 24;    // 0 or 24

    // Gate-epilogue element assignment: thread handles 4 elems, same b
    const int e0 = tid * 4;
    const int bb = e0 >> 4;           // 0..31
    const int jj = e0 & 15;           // 0,4,8,12

    for (int t = 0; t < T_; t++) {
        // Prefetch ig (3 gates x float4) and exact-fp32 h_prev — hidden under MMA
        const float* igb = g_ig + ((size_t)t * 128 + rowbase + bb) * 1536 + colbase + jj;
        float4 igr = __ldg((const float4*)(igb));
        float4 igz = __ldg((const float4*)(igb + 512));
        float4 ign = __ldg((const float4*)(igb + 1024));
        float4 hp;
        if (t == 0) hp = make_float4(0.f, 0.f, 0.f, 0.f);
        else        hp = __ldcg((const float4*)(g_h + (rowbase + bb) * 512 + colbase + jj));

        // hg tile (32x48) = Hs @ Ws^T
        float c0[4] = {0, 0, 0, 0}, c1[4] = {0, 0, 0, 0}, c2[4] = {0, 0, 0, 0};
        #pragma unroll 8
        for (int kb = 0; kb < 512; kb += 8) {
            unsigned a0 = Hs[(mrow + gid) * WS_PITCH + kb + tig];
            unsigned a1 = Hs[(mrow + gid + 8) * WS_PITCH + kb + tig];
            unsigned a2 = Hs[(mrow + gid) * WS_PITCH + kb + tig + 4];
            unsigned a3 = Hs[(mrow + gid + 8) * WS_PITCH + kb + tig + 4];
            unsigned b0, b1;
            b0 = Ws[(ncol + gid) * WS_PITCH + kb + tig];
            b1 = Ws[(ncol + gid) * WS_PITCH + kb + tig + 4];
            mma8(c0, a0, a1, a2, a3, b0, b1);
            b0 = Ws[(ncol + 8 + gid) * WS_PITCH + kb + tig];
            b1 = Ws[(ncol + 8 + gid) * WS_PITCH + kb + tig + 4];
            mma8(c1, a0, a1, a2, a3, b0, b1);
            b0 = Ws[(ncol + 16 + gid) * WS_PITCH + kb + tig];
            b1 = Ws[(ncol + 16 + gid) * WS_PITCH + kb + tig + 4];
            mma8(c2, a0, a1, a2, a3, b0, b1);
        }
        // Park hg in SMEM for the elementwise epilogue
        {
            int r0 = mrow + gid, r1 = r0 + 8, cb = ncol + 2 * tig;
            Sg[r0 * SG_PITCH + cb]          = c0[0];
            Sg[r0 * SG_PITCH + cb + 1]      = c0[1];
            Sg[r1 * SG_PITCH + cb]          = c0[2];
            Sg[r1 * SG_PITCH + cb + 1]      = c0[3];
            Sg[r0 * SG_PITCH + cb + 8]      = c1[0];
            Sg[r0 * SG_PITCH + cb + 9]      = c1[1];
            Sg[r1 * SG_PITCH + cb + 8]      = c1[2];
            Sg[r1 * SG_PITCH + cb + 9]      = c1[3];
            Sg[r0 * SG_PITCH + cb + 16]     = c2[0];
            Sg[r0 * SG_PITCH + cb + 17]     = c2[1];
            Sg[r1 * SG_PITCH + cb + 16]     = c2[2];
            Sg[r1 * SG_PITCH + cb + 17]     = c2[3];
        }
        __syncthreads();

        // Gate math for owned 32x16 tile (4 elems/thread), exact fp32
        {
            float igr_a[4] = {igr.x, igr.y, igr.z, igr.w};
            float igz_a[4] = {igz.x, igz.y, igz.z, igz.w};
            float ign_a[4] = {ign.x, ign.y, ign.z, ign.w};
            float hp_a[4]  = {hp.x, hp.y, hp.z, hp.w};
            float hnew[4];
            #pragma unroll
            for (int i = 0; i < 4; i++) {
                int j  = jj + i;
                float hr = Sg[bb * SG_PITCH + j];
                float hz = Sg[bb * SG_PITCH + 16 + j];
                float hn = Sg[bb * SG_PITCH + 32 + j];
                float bnv = __ldg(bn + colbase + j);
                float r = sigf(igr_a[i] + hr);
                float z = sigf(igz_a[i] + hz);
                float n = tanhf(ign_a[i] + r * (hn + bnv));
                hnew[i] = (1.0f - z) * n + z * hp_a[i];
            }
            *(float4*)(g_h + (rowbase + bb) * 512 + colbase + jj) =
                make_float4(hnew[0], hnew[1], hnew[2], hnew[3]);
        }

        // Grid barrier (monotonic, replay-safe)
        __threadfence();
        __syncthreads();
        if (tid == 0) {
            unsigned long long ticket = atomicAdd(&g_bar, 1ULL);
            unsigned long long target = (ticket / G + 1ULL) * G;
            volatile unsigned long long* bp = &g_bar;
            while (*bp < target) { }
        }
        __syncthreads();
        __threadfence();

        // Restage h tile (32 x 512) as TF32 for next step
        if (t < T_ - 1) {
            for (int i = tid; i < 32 * 128; i += 128) {
                int r  = i >> 7;
                int c4 = (i & 127) * 4;
                float4 v = __ldcg((const float4*)(g_h + (rowbase + r) * 512 + c4));
                uint4 u = make_uint4(f2tf(v.x), f2tf(v.y), f2tf(v.z), f2tf(v.w));
                *(uint4*)&Hs[r * WS_PITCH + c4] = u;
            }
            __syncthreads();
        }
    }
}

// ===========================================================================
// Kernel 3: out = h_final @ Wlin^T + blin; split into [mu.ravel(); logvar.ravel()]
// ===========================================================================
__global__ void __launch_bounds__(256) k_out(const float* __restrict__ Wlin,
                                             const float* __restrict__ blin,
                                             float* __restrict__ out) {
    int idx = blockIdx.x * 256 + threadIdx.x;   // 0..65535
    int b = idx >> 9;
    int n = idx & 511;
    const float* hrow = g_h + b * 512;
    const float* wrow = Wlin + (size_t)n * 512;
    float acc = __ldg(blin + n);
    #pragma unroll 8
    for (int k = 0; k < 512; k += 4) {
        float4 hv = __ldcg((const float4*)(hrow + k));
        float4 wv = __ldg((const float4*)(wrow + k));
        acc += hv.x * wv.x + hv.y * wv.y + hv.z * wv.z + hv.w * wv.w;
    }
    if (n < L_) out[b * L_ + n] = acc;                       // mu
    else        out[(size_t)B_ * L_ + b * L_ + (n - L_)] = acc;  // logvar
}

// ===========================================================================
extern "C" void kernel_launch(void* const* d_in, const int* in_sizes, int n_in,
                              void* d_out, int out_size) {
    const float* x    = (const float*)d_in[0];
    const float* Wih  = (const float*)d_in[1];
    const float* Whh  = (const float*)d_in[2];
    const float* b    = (const float*)d_in[3];
    const float* bn   = (const float*)d_in[4];
    const float* Wlin = (const float*)d_in[5];
    const float* blin = (const float*)d_in[6];
    float* out = (float*)d_out;

    cudaFuncSetAttribute(k_rec, cudaFuncAttributeMaxDynamicSharedMemorySize,
                         SMEM_K2_BYTES);

    dim3 g1(12, 512);
    k_igemm<<<g1, 256>>>(x, Wih, b);
    k_rec<<<128, 128, SMEM_K2_BYTES>>>(Whh, bn);
    k_out<<<256, 256>>>(Wlin, blin, out);
}

// round 3
// speedup vs baseline: 1.0154x; 1.0154x over previous
#include <cuda_runtime.h>

// Problem dims
#define B_  128
#define T_  512
#define D_  512
#define H_  512
#define L_  256

// ---------------------------------------------------------------------------
// Device scratch (allocation-free rule: __device__ globals)
// ---------------------------------------------------------------------------
__device__ float g_ig[(size_t)T_ * B_ * 3 * H_];   // (T, B, 3H) input gates
__device__ float g_h[B_ * H_];                      // recurrent state
__device__ unsigned long long g_bar4[4 * 16];       // 4 row-group barriers, 128B apart

// ---------------------------------------------------------------------------
// Helpers
// ---------------------------------------------------------------------------
__device__ __forceinline__ unsigned f2tf(float f) {
    unsigned u;
    asm("cvt.rna.tf32.f32 %0, %1;" : "=r"(u) : "f"(f));
    return u;
}

__device__ __forceinline__ void mma8(float c[4],
                                     unsigned a0, unsigned a1, unsigned a2, unsigned a3,
                                     unsigned b0, unsigned b1) {
    asm volatile(
        "mma.sync.aligned.m16n8k8.row.col.f32.tf32.tf32.f32 "
        "{%0,%1,%2,%3}, {%4,%5,%6,%7}, {%8,%9}, {%0,%1,%2,%3};"
        : "+f"(c[0]), "+f"(c[1]), "+f"(c[2]), "+f"(c[3])
        : "r"(a0), "r"(a1), "r"(a2), "r"(a3), "r"(b0), "r"(b1));
}

__device__ __forceinline__ float sigf(float x) {
    return 1.0f / (1.0f + __expf(-x));
}

// ===========================================================================
// Kernel 1: IG[t,b,:] = x[b,t,:] @ Wih^T + b   (UNCHANGED from round 2: 857us)
// ===========================================================================
__global__ void __launch_bounds__(256) k_igemm(const float* __restrict__ x,
                                               const float* __restrict__ Wih,
                                               const float* __restrict__ bias) {
    __shared__ unsigned As[128][20];
    __shared__ unsigned Bs[128][20];

    const int t   = blockIdx.y;
    const int n0  = blockIdx.x * 128;
    const int tid = threadIdx.x;
    const int w    = tid >> 5;
    const int lane = tid & 31;
    const int gid  = lane >> 2;
    const int tig  = lane & 3;
    const int mrow = (w >> 2) * 64;
    const int ncol = (w & 3) * 32;

    float acc[4][4][4];
    #pragma unroll
    for (int i = 0; i < 4; i++)
        #pragma unroll
        for (int j = 0; j < 4; j++)
            #pragma unroll
            for (int q = 0; q < 4; q++) acc[i][j][q] = 0.0f;

    for (int k0 = 0; k0 < 512; k0 += 16) {
        #pragma unroll
        for (int it = 0; it < 2; it++) {
            int i  = tid + it * 256;
            int r  = i >> 2;
            int c4 = (i & 3) * 4;
            float4 v = *(const float4*)(x + ((size_t)r * 512 + t) * 512 + k0 + c4);
            As[r][c4 + 0] = f2tf(v.x);
            As[r][c4 + 1] = f2tf(v.y);
            As[r][c4 + 2] = f2tf(v.z);
            As[r][c4 + 3] = f2tf(v.w);
        }
        #pragma unroll
        for (int it = 0; it < 2; it++) {
            int i  = tid + it * 256;
            int r  = i >> 2;
            int c4 = (i & 3) * 4;
            float4 v = *(const float4*)(Wih + (size_t)(n0 + r) * 512 + k0 + c4);
            Bs[r][c4 + 0] = f2tf(v.x);
            Bs[r][c4 + 1] = f2tf(v.y);
            Bs[r][c4 + 2] = f2tf(v.z);
            Bs[r][c4 + 3] = f2tf(v.w);
        }
        __syncthreads();

        #pragma unroll
        for (int ks = 0; ks < 2; ks++) {
            const int kb = ks * 8;
            unsigned a[4][4];
            #pragma unroll
            for (int mt = 0; mt < 4; mt++) {
                int r = mrow + mt * 16 + gid;
                a[mt][0] = As[r][kb + tig];
                a[mt][1] = As[r + 8][kb + tig];
                a[mt][2] = As[r][kb + tig + 4];
                a[mt][3] = As[r + 8][kb + tig + 4];
            }
            #pragma unroll
            for (int nt = 0; nt < 4; nt++) {
                int n = ncol + nt * 8 + gid;
                unsigned b0 = Bs[n][kb + tig];
                unsigned b1 = Bs[n][kb + tig + 4];
                #pragma unroll
                for (int mt = 0; mt < 4; mt++)
                    mma8(acc[mt][nt], a[mt][0], a[mt][1], a[mt][2], a[mt][3], b0, b1);
            }
        }
        __syncthreads();
    }

    #pragma unroll
    for (int mt = 0; mt < 4; mt++) {
        #pragma unroll
        for (int nt = 0; nt < 4; nt++) {
            int r0 = mrow + mt * 16 + gid;
            int c0 = n0 + ncol + nt * 8 + 2 * tig;
            float bv0 = __ldg(bias + c0);
            float bv1 = __ldg(bias + c0 + 1);
            size_t base0 = ((size_t)t * 128 + r0) * 1536 + c0;
            size_t base1 = ((size_t)t * 128 + r0 + 8) * 1536 + c0;
            *(float2*)&g_ig[base0] = make_float2(acc[mt][nt][0] + bv0, acc[mt][nt][1] + bv1);
            *(float2*)&g_ig[base1] = make_float2(acc[mt][nt][2] + bv0, acc[mt][nt][3] + bv1);
        }
    }
}

// ===========================================================================
// Kernel 2: persistent GRU recurrence.
//   grid = 128 CTAs (4 row-groups x 32 col-groups), 256 threads (8 warps).
//   CTA owns h rows [mg*32, mg*32+32), h cols [cg*16, cg*16+16);
//   computes hg tile 32 x 48 (3 gates x 16 cols).
//   Warp layout: mgrp = w>>2 (16-row half), kgrp = w&3 (K slice of 128).
//   Each warp: 16 x 48 over its K slice -> partials in Sg[kgrp].
//   Barrier: per-row-group monotonic counter (fan-in 32), replay-safe.
// ===========================================================================
#define WS_PITCH 516
#define SG_PITCH 52
#define SMEM_K2_WORDS (48 * WS_PITCH + 32 * WS_PITCH + 4 * 32 * SG_PITCH)
#define SMEM_K2_BYTES (SMEM_K2_WORDS * 4)

__global__ void __launch_bounds__(256) k_rec(const float* __restrict__ Whh,
                                             const float* __restrict__ bn) {
    extern __shared__ unsigned smem[];
    unsigned* Ws = smem;                           // [48][516] tf32 Whh slice
    unsigned* Hs = smem + 48 * WS_PITCH;           // [32][516] tf32 h tile
    float*    Sg = (float*)(smem + 80 * WS_PITCH); // [4][32][52] K-partial hg

    const int tid  = threadIdx.x;
    const int lane = tid & 31;
    const int w    = tid >> 5;
    const int gid  = lane >> 2;
    const int tig  = lane & 3;
    const int mg   = blockIdx.x >> 5;     // 0..3 row group
    const int cg   = blockIdx.x & 31;     // 0..31 col group
    const int rowbase = mg * 32;
    const int colbase = cg * 16;

    // Load Whh slice: local row lr = gate*16 + jj  <->  Whh row gate*512 + colbase + jj
    for (int i = tid; i < 48 * 128; i += 256) {
        int lr   = i >> 7;
        int c4   = (i & 127) * 4;
        int grow = (lr >> 4) * 512 + colbase + (lr & 15);
        float4 v = *(const float4*)(Whh + (size_t)grow * 512 + c4);
        uint4 u = make_uint4(f2tf(v.x), f2tf(v.y), f2tf(v.z), f2tf(v.w));
        *(uint4*)&Ws[lr * WS_PITCH + c4] = u;
    }
    // Zero Hs (h0 = 0)
    for (int i = tid; i < 32 * WS_PITCH; i += 256) Hs[i] = 0u;
    __syncthreads();

    // Warp MMA assignment
    const int mrow  = (w >> 2) * 16;      // 0 or 16
    const int kbase = (w & 3) * 128;      // K slice start
    float* Sgk = Sg + (w & 3) * 32 * SG_PITCH;

    // Gate-epilogue: each thread handles 2 elems (same b), e0 = tid*2
    const int bb = tid >> 3;              // 0..31
    const int jj = (tid * 2) & 15;        // 0,2,...,14
    const float bn0 = __ldg(bn + colbase + jj);
    const float bn1 = __ldg(bn + colbase + jj + 1);

    volatile unsigned long long* barp = &g_bar4[mg * 16];

    for (int t = 0; t < T_; t++) {
        // Prefetch ig (3 gates) and exact-fp32 h_prev — hidden under MMA
        const float* igb = g_ig + ((size_t)t * 128 + rowbase + bb) * 1536 + colbase + jj;
        float2 igr = __ldg((const float2*)(igb));
        float2 igz = __ldg((const float2*)(igb + 512));
        float2 ign = __ldg((const float2*)(igb + 1024));
        float2 hp;
        if (t == 0) hp = make_float2(0.f, 0.f);
        else        hp = __ldcg((const float2*)(g_h + (rowbase + bb) * 512 + colbase + jj));

        // Warp: 16x48 partial over K slice of 128
        float c[6][4];
        #pragma unroll
        for (int n = 0; n < 6; n++)
            #pragma unroll
            for (int q = 0; q < 4; q++) c[n][q] = 0.0f;

        #pragma unroll 4
        for (int ki = 0; ki < 16; ki++) {
            const int kb = kbase + ki * 8;
            unsigned a0 = Hs[(mrow + gid) * WS_PITCH + kb + tig];
            unsigned a1 = Hs[(mrow + gid + 8) * WS_PITCH + kb + tig];
            unsigned a2 = Hs[(mrow + gid) * WS_PITCH + kb + tig + 4];
            unsigned a3 = Hs[(mrow + gid + 8) * WS_PITCH + kb + tig + 4];
            unsigned bregs[12];
            #pragma unroll
            for (int n = 0; n < 6; n++) {
                bregs[2 * n]     = Ws[(n * 8 + gid) * WS_PITCH + kb + tig];
                bregs[2 * n + 1] = Ws[(n * 8 + gid) * WS_PITCH + kb + tig + 4];
            }
            #pragma unroll
            for (int n = 0; n < 6; n++)
                mma8(c[n], a0, a1, a2, a3, bregs[2 * n], bregs[2 * n + 1]);
        }

        // Park K-partials in Sg[kgrp]
        {
            int r0 = mrow + gid, r1 = r0 + 8;
            #pragma unroll
            for (int n = 0; n < 6; n++) {
                int cb = n * 8 + 2 * tig;
                *(float2*)&Sgk[r0 * SG_PITCH + cb] = make_float2(c[n][0], c[n][1]);
                *(float2*)&Sgk[r1 * SG_PITCH + cb] = make_float2(c[n][2], c[n][3]);
            }
        }
        __syncthreads();

        // Gate math for 2 owned elems, fp32 exact; sum the 4 K-partials
        {
            float hr0 = 0.f, hr1 = 0.f, hz0 = 0.f, hz1 = 0.f, hn0 = 0.f, hn1 = 0.f;
            #pragma unroll
            for (int k = 0; k < 4; k++) {
                const float* s = Sg + k * 32 * SG_PITCH + bb * SG_PITCH;
                float2 vr = *(const float2*)(s + jj);
                float2 vz = *(const float2*)(s + 16 + jj);
                float2 vn = *(const float2*)(s + 32 + jj);
                hr0 += vr.x; hr1 += vr.y;
                hz0 += vz.x; hz1 += vz.y;
                hn0 += vn.x; hn1 += vn.y;
            }
            float r0 = sigf(igr.x + hr0);
            float r1 = sigf(igr.y + hr1);
            float z0 = sigf(igz.x + hz0);
            float z1 = sigf(igz.y + hz1);
            float n0 = tanhf(ign.x + r0 * (hn0 + bn0));
            float n1 = tanhf(ign.y + r1 * (hn1 + bn1));
            float h0 = (1.0f - z0) * n0 + z0 * hp.x;
            float h1 = (1.0f - z1) * n1 + z1 * hp.y;
            *(float2*)(g_h + (rowbase + bb) * 512 + colbase + jj) = make_float2(h0, h1);
        }

        // Row-group barrier (monotonic, replay-safe; fan-in 32)
        __threadfence();
        __syncthreads();
        if (tid == 0) {
            unsigned long long ticket = atomicAdd(&g_bar4[mg * 16], 1ULL);
            unsigned long long target = (ticket / 32ULL + 1ULL) * 32ULL;
            while (*barp < target) { }
        }
        __syncthreads();
        __threadfence();

        // Restage h tile (32 x 512) as TF32 for next step
        if (t < T_ - 1) {
            for (int i = tid; i < 32 * 128; i += 256) {
                int r  = i >> 7;
                int c4 = (i & 127) * 4;
                float4 v = __ldcg((const float4*)(g_h + (rowbase + r) * 512 + c4));
                uint4 u = make_uint4(f2tf(v.x), f2tf(v.y), f2tf(v.z), f2tf(v.w));
                *(uint4*)&Hs[r * WS_PITCH + c4] = u;
            }
            __syncthreads();
        }
    }
}

// ===========================================================================
// Kernel 3: out = h_final @ Wlin^T + blin; split into [mu.ravel(); logvar.ravel()]
// ===========================================================================
__global__ void __launch_bounds__(256) k_out(const float* __restrict__ Wlin,
                                             const float* __restrict__ blin,
                                             float* __restrict__ out) {
    int idx = blockIdx.x * 256 + threadIdx.x;   // 0..65535
    int b = idx >> 9;
    int n = idx & 511;
    const float* hrow = g_h + b * 512;
    const float* wrow = Wlin + (size_t)n * 512;
    float acc = __ldg(blin + n);
    #pragma unroll 8
    for (int k = 0; k < 512; k += 4) {
        float4 hv = __ldcg((const float4*)(hrow + k));
        float4 wv = __ldg((const float4*)(wrow + k));
        acc += hv.x * wv.x + hv.y * wv.y + hv.z * wv.z + hv.w * wv.w;
    }
    if (n < L_) out[b * L_ + n] = acc;                           // mu
    else        out[(size_t)B_ * L_ + b * L_ + (n - L_)] = acc;  // logvar
}

// ===========================================================================
extern "C" void kernel_launch(void* const* d_in, const int* in_sizes, int n_in,
                              void* d_out, int out_size) {
    const float* x    = (const float*)d_in[0];
    const float* Wih  = (const float*)d_in[1];
    const float* Whh  = (const float*)d_in[2];
    const float* b    = (const float*)d_in[3];
    const float* bn   = (const float*)d_in[4];
    const float* Wlin = (const float*)d_in[5];
    const float* blin = (const float*)d_in[6];
    float* out = (float*)d_out;

    cudaFuncSetAttribute(k_rec, cudaFuncAttributeMaxDynamicSharedMemorySize,
                         SMEM_K2_BYTES);

    dim3 g1(12, 512);
    k_igemm<<<g1, 256>>>(x, Wih, b);
    k_rec<<<128, 256, SMEM_K2_BYTES>>>(Whh, bn);
    k_out<<<256, 256>>>(Wlin, blin, out);
}

// round 4
// speedup vs baseline: 1.7579x; 1.7312x over previous
#include <cuda_runtime.h>

// Problem dims
#define B_  128
#define T_  512
#define D_  512
#define H_  512
#define L_  256

// ---------------------------------------------------------------------------
// Device scratch (allocation-free rule: __device__ globals)
// ---------------------------------------------------------------------------
__device__ float    g_ig[(size_t)T_ * B_ * 3 * H_];  // (T, B, 3H) input gates
__device__ unsigned g_h[B_ * H_];                    // h exchange buffer (tf32 words)
__device__ float    g_hx[B_ * H_];                   // exact fp32 h_final for k_out
__device__ unsigned long long g_bar4[4 * 16];        // per-row-group barriers, 128B apart

// ---------------------------------------------------------------------------
// Helpers
// ---------------------------------------------------------------------------
__device__ __forceinline__ unsigned f2tf(float f) {
    unsigned u;
    asm("cvt.rna.tf32.f32 %0, %1;" : "=r"(u) : "f"(f));
    return u;
}

__device__ __forceinline__ void mma8(float c[4],
                                     unsigned a0, unsigned a1, unsigned a2, unsigned a3,
                                     unsigned b0, unsigned b1) {
    asm volatile(
        "mma.sync.aligned.m16n8k8.row.col.f32.tf32.tf32.f32 "
        "{%0,%1,%2,%3}, {%4,%5,%6,%7}, {%8,%9}, {%0,%1,%2,%3};"
        : "+f"(c[0]), "+f"(c[1]), "+f"(c[2]), "+f"(c[3])
        : "r"(a0), "r"(a1), "r"(a2), "r"(a3), "r"(b0), "r"(b1));
}

__device__ __forceinline__ float sigf(float x) {
    return 1.0f / (1.0f + __expf(-x));
}

__device__ __forceinline__ unsigned long long arrive_release(unsigned long long* p) {
    unsigned long long old;
    asm volatile("atom.add.release.gpu.u64 %0, [%1], 1;"
                 : "=l"(old) : "l"(p) : "memory");
    return old;
}

__device__ __forceinline__ unsigned long long ld_acquire(const unsigned long long* p) {
    unsigned long long v;
    asm volatile("ld.acquire.gpu.u64 %0, [%1];" : "=l"(v) : "l"(p) : "memory");
    return v;
}

// ===========================================================================
// Kernel 1: IG[t,b,:] = x[b,t,:] @ Wih^T + b   (frozen: ~857us measured)
// ===========================================================================
__global__ void __launch_bounds__(256) k_igemm(const float* __restrict__ x,
                                               const float* __restrict__ Wih,
                                               const float* __restrict__ bias) {
    __shared__ unsigned As[128][20];
    __shared__ unsigned Bs[128][20];

    const int t   = blockIdx.y;
    const int n0  = blockIdx.x * 128;
    const int tid = threadIdx.x;
    const int w    = tid >> 5;
    const int lane = tid & 31;
    const int gid  = lane >> 2;
    const int tig  = lane & 3;
    const int mrow = (w >> 2) * 64;
    const int ncol = (w & 3) * 32;

    float acc[4][4][4];
    #pragma unroll
    for (int i = 0; i < 4; i++)
        #pragma unroll
        for (int j = 0; j < 4; j++)
            #pragma unroll
            for (int q = 0; q < 4; q++) acc[i][j][q] = 0.0f;

    for (int k0 = 0; k0 < 512; k0 += 16) {
        #pragma unroll
        for (int it = 0; it < 2; it++) {
            int i  = tid + it * 256;
            int r  = i >> 2;
            int c4 = (i & 3) * 4;
            float4 v = *(const float4*)(x + ((size_t)r * 512 + t) * 512 + k0 + c4);
            As[r][c4 + 0] = f2tf(v.x);
            As[r][c4 + 1] = f2tf(v.y);
            As[r][c4 + 2] = f2tf(v.z);
            As[r][c4 + 3] = f2tf(v.w);
        }
        #pragma unroll
        for (int it = 0; it < 2; it++) {
            int i  = tid + it * 256;
            int r  = i >> 2;
            int c4 = (i & 3) * 4;
            float4 v = *(const float4*)(Wih + (size_t)(n0 + r) * 512 + k0 + c4);
            Bs[r][c4 + 0] = f2tf(v.x);
            Bs[r][c4 + 1] = f2tf(v.y);
            Bs[r][c4 + 2] = f2tf(v.z);
            Bs[r][c4 + 3] = f2tf(v.w);
        }
        __syncthreads();

        #pragma unroll
        for (int ks = 0; ks < 2; ks++) {
            const int kb = ks * 8;
            unsigned a[4][4];
            #pragma unroll
            for (int mt = 0; mt < 4; mt++) {
                int r = mrow + mt * 16 + gid;
                a[mt][0] = As[r][kb + tig];
                a[mt][1] = As[r + 8][kb + tig];
                a[mt][2] = As[r][kb + tig + 4];
                a[mt][3] = As[r + 8][kb + tig + 4];
            }
            #pragma unroll
            for (int nt = 0; nt < 4; nt++) {
                int n = ncol + nt * 8 + gid;
                unsigned b0 = Bs[n][kb + tig];
                unsigned b1 = Bs[n][kb + tig + 4];
                #pragma unroll
                for (int mt = 0; mt < 4; mt++)
                    mma8(acc[mt][nt], a[mt][0], a[mt][1], a[mt][2], a[mt][3], b0, b1);
            }
        }
        __syncthreads();
    }

    #pragma unroll
    for (int mt = 0; mt < 4; mt++) {
        #pragma unroll
        for (int nt = 0; nt < 4; nt++) {
            int r0 = mrow + mt * 16 + gid;
            int c0 = n0 + ncol + nt * 8 + 2 * tig;
            float bv0 = __ldg(bias + c0);
            float bv1 = __ldg(bias + c0 + 1);
            size_t base0 = ((size_t)t * 128 + r0) * 1536 + c0;
            size_t base1 = ((size_t)t * 128 + r0 + 8) * 1536 + c0;
            *(float2*)&g_ig[base0] = make_float2(acc[mt][nt][0] + bv0, acc[mt][nt][1] + bv1);
            *(float2*)&g_ig[base1] = make_float2(acc[mt][nt][2] + bv0, acc[mt][nt][3] + bv1);
        }
    }
}

// ===========================================================================
// Kernel 2: persistent GRU recurrence, W-in-registers version.
//   grid = 128 CTAs (4 row-groups x 32 col-groups), 256 threads (8 warps).
//   CTA: h rows [mg*32,+32), cols [cg*16,+16); hg tile 32 x 48.
//   Warp w = K-group: K slice [w*64, w*64+64). Whh fragments in registers
//   (96 regs). Each warp computes full 32x48 partial over its K slice.
//   Exchange: g_h holds tf32 words; own h kept exact in registers.
//   Barrier: per-row-group release-atomic + acquire polls (replay-safe).
// ===========================================================================
#define WS_PITCH 516
#define SG_PITCH 52
#define SMEM_K2_WORDS (80 * WS_PITCH)      // Ws[48][516] + Hs[32][516]; Sg aliases Ws
#define SMEM_K2_BYTES (SMEM_K2_WORDS * 4)

__global__ void __launch_bounds__(256, 1) k_rec(const float* __restrict__ Whh,
                                                const float* __restrict__ bn) {
    extern __shared__ unsigned smem[];
    unsigned* Ws = smem;                     // [48][516] (init only)
    unsigned* Hs = smem + 48 * WS_PITCH;     // [32][516] tf32 h tile
    float*    Sg = (float*)smem;             // [8][32][52] K-partials (aliases Ws)
    __shared__ unsigned long long s_target;

    const int tid  = threadIdx.x;
    const int lane = tid & 31;
    const int w    = tid >> 5;
    const int gid  = lane >> 2;
    const int tig  = lane & 3;
    const int mg   = blockIdx.x >> 5;     // 0..3 row group
    const int cg   = blockIdx.x & 31;     // 0..31 col group
    const int rowbase = mg * 32;
    const int colbase = cg * 16;

    // --- Stage Whh slice into SMEM (tf32): local row lr = gate*16 + col ---
    for (int i = tid; i < 48 * 128; i += 256) {
        int lr   = i >> 7;
        int c4   = (i & 127) * 4;
        int grow = (lr >> 4) * 512 + colbase + (lr & 15);
        float4 v = *(const float4*)(Whh + (size_t)grow * 512 + c4);
        uint4 u = make_uint4(f2tf(v.x), f2tf(v.y), f2tf(v.z), f2tf(v.w));
        *(uint4*)&Ws[lr * WS_PITCH + c4] = u;
    }
    for (int i = tid; i < 32 * WS_PITCH; i += 256) Hs[i] = 0u;  // h0 = 0
    __syncthreads();

    // --- Pull per-warp W fragments into registers: [kt 0..7][nt 0..5][2] ---
    const int kbase = w * 64;
    unsigned wf[8][6][2];
    #pragma unroll
    for (int kt = 0; kt < 8; kt++)
        #pragma unroll
        for (int nt = 0; nt < 6; nt++) {
            int base = (nt * 8 + gid) * WS_PITCH + kbase + kt * 8 + tig;
            wf[kt][nt][0] = Ws[base];
            wf[kt][nt][1] = Ws[base + 4];
        }
    __syncthreads();   // Ws reads done; Sg may overwrite from here on

    // Gate-epilogue assignment: thread -> 2 elems (bb, jj..jj+1)
    const int bb = tid >> 3;              // 0..31
    const int jj = (tid * 2) & 15;        // 0,2,...,14
    const float bn0 = __ldg(bn + colbase + jj);
    const float bn1 = __ldg(bn + colbase + jj + 1);
    float2 hp = make_float2(0.0f, 0.0f);  // own-tile exact h_prev (registers)

    float* Sgw = Sg + w * 32 * SG_PITCH;
    unsigned long long* barp = &g_bar4[mg * 16];

    for (int t = 0; t < T_; t++) {
        // Prefetch ig (overlaps MMA)
        const float* igb = g_ig + ((size_t)t * 128 + rowbase + bb) * 1536 + colbase + jj;
        float2 igr = __ldg((const float2*)(igb));
        float2 igz = __ldg((const float2*)(igb + 512));
        float2 ign = __ldg((const float2*)(igb + 1024));

        // --- Warp: 32x48 partial over its K slice of 64 ---
        float c[2][6][4];
        #pragma unroll
        for (int m = 0; m < 2; m++)
            #pragma unroll
            for (int n = 0; n < 6; n++)
                #pragma unroll
                for (int q = 0; q < 4; q++) c[m][n][q] = 0.0f;

        #pragma unroll
        for (int kt = 0; kt < 8; kt++) {
            const int kb = kbase + kt * 8;
            unsigned a[2][4];
            #pragma unroll
            for (int m = 0; m < 2; m++) {
                int r = m * 16 + gid;
                a[m][0] = Hs[r * WS_PITCH + kb + tig];
                a[m][1] = Hs[(r + 8) * WS_PITCH + kb + tig];
                a[m][2] = Hs[r * WS_PITCH + kb + tig + 4];
                a[m][3] = Hs[(r + 8) * WS_PITCH + kb + tig + 4];
            }
            #pragma unroll
            for (int n = 0; n < 6; n++) {
                mma8(c[0][n], a[0][0], a[0][1], a[0][2], a[0][3],
                     wf[kt][n][0], wf[kt][n][1]);
                mma8(c[1][n], a[1][0], a[1][1], a[1][2], a[1][3],
                     wf[kt][n][0], wf[kt][n][1]);
            }
        }

        // Park partials in Sg[w]
        #pragma unroll
        for (int m = 0; m < 2; m++) {
            int r0 = m * 16 + gid, r1 = r0 + 8;
            #pragma unroll
            for (int n = 0; n < 6; n++) {
                int cb = n * 8 + 2 * tig;
                *(float2*)&Sgw[r0 * SG_PITCH + cb] = make_float2(c[m][n][0], c[m][n][1]);
                *(float2*)&Sgw[r1 * SG_PITCH + cb] = make_float2(c[m][n][2], c[m][n][3]);
            }
        }
        __syncthreads();

        // --- Gate epilogue: sum 8 K-partials, fp32 exact ---
        {
            float hr0 = 0.f, hr1 = 0.f, hz0 = 0.f, hz1 = 0.f, hn0 = 0.f, hn1 = 0.f;
            #pragma unroll
            for (int k = 0; k < 8; k++) {
                const float* s = Sg + k * 32 * SG_PITCH + bb * SG_PITCH;
                float2 vr = *(const float2*)(s + jj);
                float2 vz = *(const float2*)(s + 16 + jj);
                float2 vn = *(const float2*)(s + 32 + jj);
                hr0 += vr.x; hr1 += vr.y;
                hz0 += vz.x; hz1 += vz.y;
                hn0 += vn.x; hn1 += vn.y;
            }
            float r0 = sigf(igr.x + hr0);
            float r1 = sigf(igr.y + hr1);
            float z0 = sigf(igz.x + hz0);
            float z1 = sigf(igz.y + hz1);
            float n0 = tanhf(ign.x + r0 * (hn0 + bn0));
            float n1 = tanhf(ign.y + r1 * (hn1 + bn1));
            float h0 = (1.0f - z0) * n0 + z0 * hp.x;
            float h1 = (1.0f - z1) * n1 + z1 * hp.y;
            hp = make_float2(h0, h1);

            if (t < T_ - 1) {
                // tf32 exchange word pair
                uint2 uv = make_uint2(f2tf(h0), f2tf(h1));
                unsigned* dst = g_h + (rowbase + bb) * 512 + colbase + jj;
                asm volatile("st.global.cg.v2.u32 [%0], {%1,%2};"
                             :: "l"(dst), "r"(uv.x), "r"(uv.y) : "memory");
            } else {
                // exact fp32 for k_out
                *(float2*)(g_hx + (rowbase + bb) * 512 + colbase + jj) =
                    make_float2(h0, h1);
            }
        }

        if (t == T_ - 1) break;

        // --- Row-group barrier (monotonic ticket, replay-safe) ---
        __syncthreads();   // all exchange stores issued
        if (tid == 0) {
            unsigned long long ticket = arrive_release(barp);
            s_target = (ticket / 32ULL + 1ULL) * 32ULL;
        }
        __syncthreads();   // s_target visible
        {
            unsigned long long tgt = s_target;
            if (lane == 0) {
                while (ld_acquire(barp) < tgt) { }
            }
            __syncwarp();
        }

        // --- Restage: warp w copies rows [w*4, w*4+4) raw tf32 words ---
        #pragma unroll
        for (int r = 0; r < 4; r++) {
            int row = w * 4 + r;
            const uint4* src = (const uint4*)(g_h + (rowbase + row) * 512);
            #pragma unroll
            for (int cc = 0; cc < 4; cc++) {
                uint4 v;
                asm volatile("ld.global.cg.v4.u32 {%0,%1,%2,%3}, [%4];"
                             : "=r"(v.x), "=r"(v.y), "=r"(v.z), "=r"(v.w)
                             : "l"(src + lane + cc * 32));
                *(uint4*)&Hs[row * WS_PITCH + (lane + cc * 32) * 4] = v;
            }
        }
        __syncthreads();   // Hs ready for next step
    }
}

// ===========================================================================
// Kernel 3: out = h_final @ Wlin^T + blin; [mu.ravel(); logvar.ravel()]
// ===========================================================================
__global__ void __launch_bounds__(256) k_out(const float* __restrict__ Wlin,
                                             const float* __restrict__ blin,
                                             float* __restrict__ out) {
    int idx = blockIdx.x * 256 + threadIdx.x;   // 0..65535
    int b = idx >> 9;
    int n = idx & 511;
    const float* hrow = g_hx + b * 512;
    const float* wrow = Wlin + (size_t)n * 512;
    float acc = __ldg(blin + n);
    #pragma unroll 8
    for (int k = 0; k < 512; k += 4) {
        float4 hv = __ldcg((const float4*)(hrow + k));
        float4 wv = __ldg((const float4*)(wrow + k));
        acc += hv.x * wv.x + hv.y * wv.y + hv.z * wv.z + hv.w * wv.w;
    }
    if (n < L_) out[b * L_ + n] = acc;                           // mu
    else        out[(size_t)B_ * L_ + b * L_ + (n - L_)] = acc;  // logvar
}

// ===========================================================================
extern "C" void kernel_launch(void* const* d_in, const int* in_sizes, int n_in,
                              void* d_out, int out_size) {
    const float* x    = (const float*)d_in[0];
    const float* Wih  = (const float*)d_in[1];
    const float* Whh  = (const float*)d_in[2];
    const float* b    = (const float*)d_in[3];
    const float* bn   = (const float*)d_in[4];
    const float* Wlin = (const float*)d_in[5];
    const float* blin = (const float*)d_in[6];
    float* out = (float*)d_out;

    cudaFuncSetAttribute(k_rec, cudaFuncAttributeMaxDynamicSharedMemorySize,
                         SMEM_K2_BYTES);

    dim3 g1(12, 512);
    k_igemm<<<g1, 256>>>(x, Wih, b);
    k_rec<<<128, 256, SMEM_K2_BYTES>>>(Whh, bn);
    k_out<<<256, 256>>>(Wlin, blin, out);
}

// round 5
// speedup vs baseline: 1.9500x; 1.1093x over previous
#include <cuda_runtime.h>

// Problem dims
#define B_  128
#define T_  512
#define D_  512
#define H_  512
#define L_  256

// ---------------------------------------------------------------------------
// Device scratch (allocation-free rule: __device__ globals)
// ---------------------------------------------------------------------------
__device__ float    g_ig[(size_t)T_ * B_ * 3 * H_];  // (T, B, 3H) input gates
__device__ unsigned g_h[B_ * H_];                    // h exchange buffer (tf32 words)
__device__ float    g_hx[B_ * H_];                   // exact fp32 h_final for k_out
__device__ unsigned long long g_flag[128 * 16];      // per-CTA step counters, 128B apart

// ---------------------------------------------------------------------------
// Helpers
// ---------------------------------------------------------------------------
__device__ __forceinline__ unsigned f2tf(float f) {
    unsigned u;
    asm("cvt.rna.tf32.f32 %0, %1;" : "=r"(u) : "f"(f));
    return u;
}

__device__ __forceinline__ void mma8(float c[4],
                                     unsigned a0, unsigned a1, unsigned a2, unsigned a3,
                                     unsigned b0, unsigned b1) {
    asm volatile(
        "mma.sync.aligned.m16n8k8.row.col.f32.tf32.tf32.f32 "
        "{%0,%1,%2,%3}, {%4,%5,%6,%7}, {%8,%9}, {%0,%1,%2,%3};"
        : "+f"(c[0]), "+f"(c[1]), "+f"(c[2]), "+f"(c[3])
        : "r"(a0), "r"(a1), "r"(a2), "r"(a3), "r"(b0), "r"(b1));
}

__device__ __forceinline__ float sigf(float x) {
    return 1.0f / (1.0f + __expf(-x));
}

__device__ __forceinline__ unsigned long long arrive_release(unsigned long long* p) {
    unsigned long long old;
    asm volatile("atom.add.release.gpu.u64 %0, [%1], 1;"
                 : "=l"(old) : "l"(p) : "memory");
    return old;
}

__device__ __forceinline__ unsigned long long ld_acquire(const unsigned long long* p) {
    unsigned long long v;
    asm volatile("ld.acquire.gpu.u64 %0, [%1];" : "=l"(v) : "l"(p) : "memory");
    return v;
}

// ===========================================================================
// Kernel 0: zero the producer flags (runs in-graph every replay)
// ===========================================================================
__global__ void k_zero() {
    for (int i = threadIdx.x; i < 128 * 16; i += 256) g_flag[i] = 0ULL;
}

// ===========================================================================
// Kernel 1: IG[t,b,:] = x[b,t,:] @ Wih^T + b
//   cp.async double-buffered fp32 tiles; cvt.tf32 at fragment load.
//   grid (12, 512), 256 thr, CTA tile 128x128, k-chunk 16, one sync/chunk.
// ===========================================================================
__global__ void __launch_bounds__(256, 2) k_igemm(const float* __restrict__ x,
                                                  const float* __restrict__ Wih,
                                                  const float* __restrict__ bias) {
    __shared__ float As[2][128][20];
    __shared__ float Bs[2][128][20];

    const int t   = blockIdx.y;
    const int n0  = blockIdx.x * 128;
    const int tid = threadIdx.x;
    const int w    = tid >> 5;
    const int lane = tid & 31;
    const int gid  = lane >> 2;
    const int tig  = lane & 3;
    const int mrow = (w >> 2) * 64;
    const int ncol = (w & 3) * 32;

    // per-thread load slots (2 x 16B for A, 2 for B)
    const int lr  = tid >> 2;          // row for slot 0 (0..63); slot1 = +64
    const int lc4 = (tid & 3) * 4;     // col word offset

    auto issue = [&](int k0, int buf) {
        #pragma unroll
        for (int it = 0; it < 2; it++) {
            int r = lr + it * 64;
            const float* ga = x + ((size_t)r * 512 + t) * 512 + k0 + lc4;
            unsigned sa = (unsigned)__cvta_generic_to_shared(&As[buf][r][lc4]);
            asm volatile("cp.async.cg.shared.global [%0], [%1], 16;"
                         :: "r"(sa), "l"(ga));
            const float* gb = Wih + (size_t)(n0 + r) * 512 + k0 + lc4;
            unsigned sb = (unsigned)__cvta_generic_to_shared(&Bs[buf][r][lc4]);
            asm volatile("cp.async.cg.shared.global [%0], [%1], 16;"
                         :: "r"(sb), "l"(gb));
        }
        asm volatile("cp.async.commit_group;");
    };

    float acc[4][4][4];
    #pragma unroll
    for (int i = 0; i < 4; i++)
        #pragma unroll
        for (int j = 0; j < 4; j++)
            #pragma unroll
            for (int q = 0; q < 4; q++) acc[i][j][q] = 0.0f;

    issue(0, 0);

    for (int c = 0; c < 32; c++) {
        asm volatile("cp.async.wait_group 0;" ::: "memory");
        __syncthreads();
        if (c < 31) issue((c + 1) * 16, (c + 1) & 1);
        const int buf = c & 1;

        #pragma unroll
        for (int ks = 0; ks < 2; ks++) {
            const int kb = ks * 8;
            unsigned a[4][4];
            #pragma unroll
            for (int mt = 0; mt < 4; mt++) {
                int r = mrow + mt * 16 + gid;
                a[mt][0] = f2tf(As[buf][r][kb + tig]);
                a[mt][1] = f2tf(As[buf][r + 8][kb + tig]);
                a[mt][2] = f2tf(As[buf][r][kb + tig + 4]);
                a[mt][3] = f2tf(As[buf][r + 8][kb + tig + 4]);
            }
            #pragma unroll
            for (int nt = 0; nt < 4; nt++) {
                int n = ncol + nt * 8 + gid;
                unsigned b0 = f2tf(Bs[buf][n][kb + tig]);
                unsigned b1 = f2tf(Bs[buf][n][kb + tig + 4]);
                #pragma unroll
                for (int mt = 0; mt < 4; mt++)
                    mma8(acc[mt][nt], a[mt][0], a[mt][1], a[mt][2], a[mt][3], b0, b1);
            }
        }
        // no trailing sync: next iteration's wait+sync guards buffer reuse
    }

    #pragma unroll
    for (int mt = 0; mt < 4; mt++) {
        #pragma unroll
        for (int nt = 0; nt < 4; nt++) {
            int r0 = mrow + mt * 16 + gid;
            int c0 = n0 + ncol + nt * 8 + 2 * tig;
            float bv0 = __ldg(bias + c0);
            float bv1 = __ldg(bias + c0 + 1);
            size_t base0 = ((size_t)t * 128 + r0) * 1536 + c0;
            size_t base1 = ((size_t)t * 128 + r0 + 8) * 1536 + c0;
            *(float2*)&g_ig[base0] = make_float2(acc[mt][nt][0] + bv0, acc[mt][nt][1] + bv1);
            *(float2*)&g_ig[base1] = make_float2(acc[mt][nt][2] + bv0, acc[mt][nt][3] + bv1);
        }
    }
}

// ===========================================================================
// Kernel 2: persistent GRU recurrence, producer-flag pipelined version.
//   grid = 128 CTAs (4 row-groups x 32 col-groups), 256 threads (8 warps).
//   CTA (mg,cg): h rows [mg*32,+32), cols [cg*16,+16); hg tile 32x48.
//   Warp w = K-group [w*64,+64). Whh fragments in registers.
//   Sync: per-CTA monotonic flag; warp w polls only its 4 producer CTAs
//   (mg, w*4..w*4+3), restages its own K slice, and enters MMA sync-free
//   (Hs columns are warp-private).
// ===========================================================================
#define WS_PITCH 516
#define SG_PITCH 52
#define SMEM_K2_WORDS (80 * WS_PITCH)      // Ws[48][516] + Hs[32][516]; Sg aliases Ws
#define SMEM_K2_BYTES (SMEM_K2_WORDS * 4)

__global__ void __launch_bounds__(256, 1) k_rec(const float* __restrict__ Whh,
                                                const float* __restrict__ bn) {
    extern __shared__ unsigned smem[];
    unsigned* Ws = smem;                     // [48][516] (init only)
    unsigned* Hs = smem + 48 * WS_PITCH;     // [32][516] tf32 h tile
    float*    Sg = (float*)smem;             // [8][32][52] K-partials (aliases Ws)

    const int tid  = threadIdx.x;
    const int lane = tid & 31;
    const int w    = tid >> 5;
    const int gid  = lane >> 2;
    const int tig  = lane & 3;
    const int mg   = blockIdx.x >> 5;     // 0..3 row group
    const int cg   = blockIdx.x & 31;     // 0..31 col group
    const int rowbase = mg * 32;
    const int colbase = cg * 16;

    // --- Stage Whh slice into SMEM (tf32): local row lr = gate*16 + col ---
    for (int i = tid; i < 48 * 128; i += 256) {
        int lr   = i >> 7;
        int c4   = (i & 127) * 4;
        int grow = (lr >> 4) * 512 + colbase + (lr & 15);
        float4 v = *(const float4*)(Whh + (size_t)grow * 512 + c4);
        uint4 u = make_uint4(f2tf(v.x), f2tf(v.y), f2tf(v.z), f2tf(v.w));
        *(uint4*)&Ws[lr * WS_PITCH + c4] = u;
    }
    for (int i = tid; i < 32 * WS_PITCH; i += 256) Hs[i] = 0u;  // h0 = 0
    __syncthreads();

    // --- Pull per-warp W fragments into registers: [kt 0..7][nt 0..5][2] ---
    const int kbase = w * 64;
    unsigned wf[8][6][2];
    #pragma unroll
    for (int kt = 0; kt < 8; kt++)
        #pragma unroll
        for (int nt = 0; nt < 6; nt++) {
            int base = (nt * 8 + gid) * WS_PITCH + kbase + kt * 8 + tig;
            wf[kt][nt][0] = Ws[base];
            wf[kt][nt][1] = Ws[base + 4];
        }
    __syncthreads();   // Ws reads done; Sg may overwrite from here on

    // Gate-epilogue assignment: thread -> 2 elems (bb, jj..jj+1)
    const int bb = tid >> 3;              // 0..31
    const int jj = (tid * 2) & 15;        // 0,2,...,14
    const float bn0 = __ldg(bn + colbase + jj);
    const float bn1 = __ldg(bn + colbase + jj + 1);
    float2 hp = make_float2(0.0f, 0.0f);  // own-tile exact h_prev (registers)

    float* Sgw = Sg + w * 32 * SG_PITCH;
    unsigned long long* myflag = &g_flag[(mg * 32 + cg) * 16];
    // Producer flags this warp depends on (lanes 0..3 each own one)
    const unsigned long long* pf =
        &g_flag[(mg * 32 + w * 4 + (lane & 3)) * 16];

    // Restage addressing: warp-private K slice, 32 rows x 64 cols
    const int rs_half = lane >> 4;            // 0/1: row parity within pair
    const int rs_c4   = (lane & 15) * 4;      // word offset within slice

    for (int t = 0; t < T_; t++) {
        // Prefetch ig (independent of flags — overlaps poll + MMA)
        const float* igb = g_ig + ((size_t)t * 128 + rowbase + bb) * 1536 + colbase + jj;
        float2 igr = __ldg((const float2*)(igb));
        float2 igz = __ldg((const float2*)(igb + 512));
        float2 ign = __ldg((const float2*)(igb + 1024));

        if (t > 0) {
            // Wait for this warp's 4 producers to finish step t-1
            if (lane < 4) {
                while (ld_acquire(pf) < (unsigned long long)t) { }
            }
            __syncwarp();
            // Restage own K slice (warp-private Hs columns, no CTA sync)
            #pragma unroll
            for (int rr = 0; rr < 16; rr++) {
                int row = rr * 2 + rs_half;
                const uint4* src =
                    (const uint4*)(g_h + (rowbase + row) * 512 + kbase + rs_c4);
                uint4 v;
                asm volatile("ld.global.cg.v4.u32 {%0,%1,%2,%3}, [%4];"
                             : "=r"(v.x), "=r"(v.y), "=r"(v.z), "=r"(v.w)
                             : "l"(src));
                *(uint4*)&Hs[row * WS_PITCH + kbase + rs_c4] = v;
            }
        }

        // --- Warp: 32x48 partial over its K slice of 64 ---
        float c[2][6][4];
        #pragma unroll
        for (int m = 0; m < 2; m++)
            #pragma unroll
            for (int n = 0; n < 6; n++)
                #pragma unroll
                for (int q = 0; q < 4; q++) c[m][n][q] = 0.0f;

        #pragma unroll
        for (int kt = 0; kt < 8; kt++) {
            const int kb = kbase + kt * 8;
            unsigned a[2][4];
            #pragma unroll
            for (int m = 0; m < 2; m++) {
                int r = m * 16 + gid;
                a[m][0] = Hs[r * WS_PITCH + kb + tig];
                a[m][1] = Hs[(r + 8) * WS_PITCH + kb + tig];
                a[m][2] = Hs[r * WS_PITCH + kb + tig + 4];
                a[m][3] = Hs[(r + 8) * WS_PITCH + kb + tig + 4];
            }
            #pragma unroll
            for (int n = 0; n < 6; n++) {
                mma8(c[0][n], a[0][0], a[0][1], a[0][2], a[0][3],
                     wf[kt][n][0], wf[kt][n][1]);
                mma8(c[1][n], a[1][0], a[1][1], a[1][2], a[1][3],
                     wf[kt][n][0], wf[kt][n][1]);
            }
        }

        // Park partials in Sg[w]
        #pragma unroll
        for (int m = 0; m < 2; m++) {
            int r0 = m * 16 + gid, r1 = r0 + 8;
            #pragma unroll
            for (int n = 0; n < 6; n++) {
                int cb = n * 8 + 2 * tig;
                *(float2*)&Sgw[r0 * SG_PITCH + cb] = make_float2(c[m][n][0], c[m][n][1]);
                *(float2*)&Sgw[r1 * SG_PITCH + cb] = make_float2(c[m][n][2], c[m][n][3]);
            }
        }
        __syncthreads();

        // --- Gate epilogue: sum 8 K-partials, fp32 exact ---
        {
            float hr0 = 0.f, hr1 = 0.f, hz0 = 0.f, hz1 = 0.f, hn0 = 0.f, hn1 = 0.f;
            #pragma unroll
            for (int k = 0; k < 8; k++) {
                const float* s = Sg + k * 32 * SG_PITCH + bb * SG_PITCH;
                float2 vr = *(const float2*)(s + jj);
                float2 vz = *(const float2*)(s + 16 + jj);
                float2 vn = *(const float2*)(s + 32 + jj);
                hr0 += vr.x; hr1 += vr.y;
                hz0 += vz.x; hz1 += vz.y;
                hn0 += vn.x; hn1 += vn.y;
            }
            float r0 = sigf(igr.x + hr0);
            float r1 = sigf(igr.y + hr1);
            float z0 = sigf(igz.x + hz0);
            float z1 = sigf(igz.y + hz1);
            float n0 = tanhf(ign.x + r0 * (hn0 + bn0));
            float n1 = tanhf(ign.y + r1 * (hn1 + bn1));
            float h0 = (1.0f - z0) * n0 + z0 * hp.x;
            float h1 = (1.0f - z1) * n1 + z1 * hp.y;
            hp = make_float2(h0, h1);

            if (t < T_ - 1) {
                uint2 uv = make_uint2(f2tf(h0), f2tf(h1));
                unsigned* dst = g_h + (rowbase + bb) * 512 + colbase + jj;
                asm volatile("st.global.cg.v2.u32 [%0], {%1,%2};"
                             :: "l"(dst), "r"(uv.x), "r"(uv.y) : "memory");
            } else {
                *(float2*)(g_hx + (rowbase + bb) * 512 + colbase + jj) =
                    make_float2(h0, h1);
            }
        }

        if (t == T_ - 1) break;

        __syncthreads();                 // all h stores issued (also guards Sg)
        if (tid == 0) arrive_release(myflag);   // flag value becomes t+1
    }
}

// ===========================================================================
// Kernel 3: out = h_final @ Wlin^T + blin; [mu.ravel(); logvar.ravel()]
// ===========================================================================
__global__ void __launch_bounds__(256) k_out(const float* __restrict__ Wlin,
                                             const float* __restrict__ blin,
                                             float* __restrict__ out) {
    int idx = blockIdx.x * 256 + threadIdx.x;   // 0..65535
    int b = idx >> 9;
    int n = idx & 511;
    const float* hrow = g_hx + b * 512;
    const float* wrow = Wlin + (size_t)n * 512;
    float acc = __ldg(blin + n);
    #pragma unroll 8
    for (int k = 0; k < 512; k += 4) {
        float4 hv = __ldcg((const float4*)(hrow + k));
        float4 wv = __ldg((const float4*)(wrow + k));
        acc += hv.x * wv.x + hv.y * wv.y + hv.z * wv.z + hv.w * wv.w;
    }
    if (n < L_) out[b * L_ + n] = acc;                           // mu
    else        out[(size_t)B_ * L_ + b * L_ + (n - L_)] = acc;  // logvar
}

// ===========================================================================
extern "C" void kernel_launch(void* const* d_in, const int* in_sizes, int n_in,
                              void* d_out, int out_size) {
    const float* x    = (const float*)d_in[0];
    const float* Wih  = (const float*)d_in[1];
    const float* Whh  = (const float*)d_in[2];
    const float* b    = (const float*)d_in[3];
    const float* bn   = (const float*)d_in[4];
    const float* Wlin = (const float*)d_in[5];
    const float* blin = (const float*)d_in[6];
    float* out = (float*)d_out;

    cudaFuncSetAttribute(k_rec, cudaFuncAttributeMaxDynamicSharedMemorySize,
                         SMEM_K2_BYTES);

    dim3 g1(12, 512);
    k_igemm<<<g1, 256>>>(x, Wih, b);
    k_zero<<<1, 256>>>();
    k_rec<<<128, 256, SMEM_K2_BYTES>>>(Whh, bn);
    k_out<<<256, 256>>>(Wlin, blin, out);
}